// round 11
// baseline (speedup 1.0000x reference)
#include <cuda_runtime.h>
#include <cuda_bf16.h>
#include <math.h>
#include <stdint.h>

#define NB 2
#define NH 16
#define NS 2048
#define ND 1024
#define HD 64
#define NM (NB*NS)
#define ROT_SCALE 0.35355339059327378f

static __device__ __nv_bfloat16 g_xh[NM*ND], g_xl[NM*ND];
static __device__ __nv_bfloat16 g_wh[4*ND*ND], g_wl[4*ND*ND];
static __device__ __nv_bfloat16 g_qh[NM*ND], g_ql[NM*ND];   // [bh][s][64]
static __device__ __nv_bfloat16 g_kh[NM*ND], g_kl[NM*ND];
static __device__ __nv_bfloat16 g_vh[NM*ND], g_vl[NM*ND];
static __device__ __nv_bfloat16 g_ah[NM*ND], g_al[NM*ND];   // [m][1024]
static __device__ float2 g_rope[NS*32];

// ---------------- helpers ----------------
__device__ __forceinline__ uint32_t smem_u32(const void* p){
    uint32_t a; asm("{ .reg .u64 t; cvta.to.shared.u64 t, %1; cvt.u32.u64 %0, t; }":"=r"(a):"l"(p)); return a;
}
__device__ __forceinline__ void ldsm4(uint32_t* r, uint32_t a){
    asm volatile("ldmatrix.sync.aligned.m8n8.x4.shared.b16 {%0,%1,%2,%3}, [%4];"
        : "=r"(r[0]),"=r"(r[1]),"=r"(r[2]),"=r"(r[3]) : "r"(a));
}
__device__ __forceinline__ void ldsm4t(uint32_t* r, uint32_t a){
    asm volatile("ldmatrix.sync.aligned.m8n8.x4.trans.shared.b16 {%0,%1,%2,%3}, [%4];"
        : "=r"(r[0]),"=r"(r[1]),"=r"(r[2]),"=r"(r[3]) : "r"(a));
}
__device__ __forceinline__ void mma16816(float* c, const uint32_t* a, uint32_t b0, uint32_t b1){
    asm volatile("mma.sync.aligned.m16n8k16.row.col.f32.bf16.bf16.f32 "
        "{%0,%1,%2,%3}, {%4,%5,%6,%7}, {%8,%9}, {%0,%1,%2,%3};"
        : "+f"(c[0]),"+f"(c[1]),"+f"(c[2]),"+f"(c[3])
        : "r"(a[0]),"r"(a[1]),"r"(a[2]),"r"(a[3]), "r"(b0),"r"(b1));
}
__device__ __forceinline__ void mma16816v(float* c, uint32_t a0, uint32_t a1, uint32_t a2, uint32_t a3,
                                          uint32_t b0, uint32_t b1){
    asm volatile("mma.sync.aligned.m16n8k16.row.col.f32.bf16.bf16.f32 "
        "{%0,%1,%2,%3}, {%4,%5,%6,%7}, {%8,%9}, {%0,%1,%2,%3};"
        : "+f"(c[0]),"+f"(c[1]),"+f"(c[2]),"+f"(c[3])
        : "r"(a0),"r"(a1),"r"(a2),"r"(a3), "r"(b0),"r"(b1));
}
// hi = {bf16(b)|bf16(a)}, lo = residual pair; exact RN numerics
__device__ __forceinline__ void split_pk(float a, float b, uint32_t& hi, uint32_t& lo){
    uint32_t h; asm("cvt.rn.bf16x2.f32 %0, %1, %2;" : "=r"(h) : "f"(b), "f"(a));
    float ha = __uint_as_float(h << 16);
    float hb = __uint_as_float(h & 0xffff0000u);
    uint32_t l; asm("cvt.rn.bf16x2.f32 %0, %1, %2;" : "=r"(l) : "f"(b - hb), "f"(a - ha));
    hi = h; lo = l;
}
__device__ __forceinline__ void cpa16(uint32_t s, const void* g){
    asm volatile("cp.async.cg.shared.global [%0], [%1], 16;"::"r"(s),"l"(g));
}
#define CPA_COMMIT() asm volatile("cp.async.commit_group;" ::: "memory")
#define CPA_WAIT(n)  asm volatile("cp.async.wait_group %0;"::"n"(n):"memory")
__device__ __forceinline__ void stg_cs2(float* p, float a, float b){
    asm volatile("st.global.cs.v2.f32 [%0], {%1,%2};" :: "l"(p), "f"(a), "f"(b) : "memory");
}
__device__ __forceinline__ void stg_cs4(float* p, float4 v){
    asm volatile("st.global.cs.v4.f32 [%0], {%1,%2,%3,%4};"
        :: "l"(p), "f"(v.x), "f"(v.y), "f"(v.z), "f"(v.w) : "memory");
}

#define SMST 144
__device__ __forceinline__ uint32_t addrA(uint32_t base, int m, int k, int lane){
    int quad=lane>>3, rr=lane&7;
    return base + (uint32_t)((m + ((quad&1)<<3) + rr)*SMST + ((k + ((quad>>1)<<3))<<1));
}
__device__ __forceinline__ uint32_t addrB(uint32_t base, int n, int k, int lane){
    int quad=lane>>3, rr=lane&7;
    return base + (uint32_t)((n + ((quad>>1)<<3) + rr)*SMST + ((k + ((quad&1)<<3))<<1));
}
__device__ __forceinline__ uint32_t addrVt(uint32_t base, int k, int n, int lane){
    int quad=lane>>3, rr=lane&7;
    return base + (uint32_t)((k + (quad<<3) + rr)*SMST + (n<<1));
}

// ---------------- prep ----------------
__global__ __launch_bounds__(256) void prep_kernel(
    const float* __restrict__ x, const float* __restrict__ Wq,
    const float* __restrict__ Wk, const float* __restrict__ Wv,
    const float* __restrict__ Wo)
{
    size_t base = ((size_t)blockIdx.x*256 + threadIdx.x)*4;
    const float* src; __nv_bfloat16 *dh, *dl; size_t off;
    if (base < (size_t)NM*ND) { off = base; src = x + off; dh = g_xh; dl = g_xl; }
    else {
        off = base - (size_t)NM*ND;
        int ws = (int)(off >> 20);
        const float* W = (ws==0)?Wq:(ws==1)?Wk:(ws==2)?Wv:Wo;
        src = W + (off & 1048575u); dh = g_wh; dl = g_wl;
    }
    float4 v = *(const float4*)src;
    uint32_t h0,l0,h1,l1;
    split_pk(v.x,v.y,h0,l0); split_pk(v.z,v.w,h1,l1);
    *(uint32_t*)(dh+off)=h0; *(uint32_t*)(dh+off+2)=h1;
    *(uint32_t*)(dl+off)=l0; *(uint32_t*)(dl+off+2)=l1;
}

__global__ __launch_bounds__(256) void rope_kernel(const float* __restrict__ invf){
    int i = blockIdx.x*256 + threadIdx.x;
    int s = i >> 5, p = i & 31;
    float sn, cs; sincosf((float)s * invf[p], &sn, &cs);
    g_rope[i] = make_float2(cs, sn);
}

// ============================================================
// GEMM: C[128x64], 128 threads, 2 CTAs/SM (unchanged from R10).
// qkv launch: blockIdx.y<4 = fill blocks (run first, overlap waves).
// ============================================================
#define G_AH 0
#define G_AL 18432
#define G_BH 36864
#define G_BL 46080
#define GSTG 55296
#define GS_SIZE (2*GSTG)

__global__ __launch_bounds__(128, 2) void gemm_tc(
    const float* __restrict__ bq, const float* __restrict__ bv,
    const float* __restrict__ bo, float* __restrict__ outp,
    float* __restrict__ qk, int mode_base)
{
    if (mode_base==0 && blockIdx.y < 4) {
        int fid = (int)blockIdx.y*32 + (int)blockIdx.x;
        int bh = fid >> 2, part = fid & 3;
        float* qkp = qk + (size_t)bh*NS*NS;
        const float4 M9 = make_float4(-1e9f,-1e9f,-1e9f,-1e9f);
        for (int qt = part; qt < 31; qt += 4) {
            const int jstart = (qt+1)*64;
            const int n = NS - jstart;
            for (int r = qt*64; r < qt*64 + 64; ++r) {
                float* rp = qkp + (size_t)r*NS + jstart;
                for (int c = (int)threadIdx.x*4; c < n; c += 512)
                    stg_cs4(rp + c, M9);
            }
        }
        return;
    }

    extern __shared__ __align__(128) char sm[];
    const uint32_t smb = smem_u32(sm);
    const int t = threadIdx.x, lane = t&31, wm = t>>5;
    const int m0 = blockIdx.x*128;
    int mode, n0;
    if (mode_base==0) { int y = blockIdx.y-4; mode = y>>4; n0 = (y&15)*64; }
    else { mode = 3; n0 = blockIdx.y*64; }
    const __nv_bfloat16* Ah = (mode_base==0)? g_xh : g_ah;
    const __nv_bfloat16* Al = (mode_base==0)? g_xl : g_al;
    const __nv_bfloat16* Wh = g_wh + (size_t)mode*ND*ND;
    const __nv_bfloat16* Wl = g_wl + (size_t)mode*ND*ND;

    float acc[2][8][4];
#pragma unroll
    for (int i=0;i<2;++i)
#pragma unroll
        for (int j=0;j<8;++j)
#pragma unroll
            for (int q=0;q<4;++q) acc[i][j][q] = 0.f;

    const int lr = t>>3, lc8 = t&7;
    auto issue = [&](int chunk, int buf){
        const int k0 = chunk*64;
        uint32_t sb = smb + buf*GSTG;
#pragma unroll
        for (int i=0;i<8;++i) {
            int r = lr + i*16;
            uint32_t so = (uint32_t)(r*SMST + lc8*16);
            size_t ga = (size_t)(m0+r)*ND + k0 + lc8*8;
            cpa16(sb + G_AH + so, Ah + ga);
            cpa16(sb + G_AL + so, Al + ga);
        }
#pragma unroll
        for (int i=0;i<4;++i) {
            int r = lr + i*16;
            uint32_t so = (uint32_t)(r*SMST + lc8*16);
            size_t gw = (size_t)(n0+r)*ND + k0 + lc8*8;
            cpa16(sb + G_BH + so, Wh + gw);
            cpa16(sb + G_BL + so, Wl + gw);
        }
        CPA_COMMIT();
    };

    issue(0, 0);
    for (int c = 0; c < 16; ++c) {
        CPA_WAIT(0);
        __syncthreads();
        if (c < 15) issue(c+1, (c+1)&1);
        uint32_t sb = smb + (c&1)*GSTG;
#pragma unroll
        for (int kk = 0; kk < 4; ++kk) {
            const int kb = kk*16;
            uint32_t ah[2][4], al[2][4], bh16[16], bl16[16];
#pragma unroll
            for (int mt=0;mt<2;++mt) {
                ldsm4(ah[mt], addrA(sb+G_AH, wm*32+mt*16, kb, lane));
                ldsm4(al[mt], addrA(sb+G_AL, wm*32+mt*16, kb, lane));
            }
#pragma unroll
            for (int tn=0;tn<4;++tn) {
                ldsm4(&bh16[tn*4], addrB(sb+G_BH, tn*16, kb, lane));
                ldsm4(&bl16[tn*4], addrB(sb+G_BL, tn*16, kb, lane));
            }
#pragma unroll
            for (int mt=0;mt<2;++mt)
#pragma unroll
                for (int nt=0;nt<8;++nt)
                    mma16816(acc[mt][nt], ah[mt], bh16[(nt>>1)*4+(nt&1)*2], bh16[(nt>>1)*4+(nt&1)*2+1]);
#pragma unroll
            for (int mt=0;mt<2;++mt)
#pragma unroll
                for (int nt=0;nt<8;++nt)
                    mma16816(acc[mt][nt], ah[mt], bl16[(nt>>1)*4+(nt&1)*2], bl16[(nt>>1)*4+(nt&1)*2+1]);
#pragma unroll
            for (int mt=0;mt<2;++mt)
#pragma unroll
                for (int nt=0;nt<8;++nt)
                    mma16816(acc[mt][nt], al[mt], bh16[(nt>>1)*4+(nt&1)*2], bh16[(nt>>1)*4+(nt&1)*2+1]);
        }
    }

#pragma unroll
    for (int mt=0;mt<2;++mt)
#pragma unroll
        for (int nt=0;nt<8;++nt) {
            int rowb = wm*32 + mt*16 + (lane>>2);
            int col  = n0 + nt*8 + ((lane&3)<<1);
            float bb0 = 0.f, bb1 = 0.f;
            if (mode==0)      { bb0 = bq[col]; bb1 = bq[col+1]; }
            else if (mode==2) { bb0 = bv[col]; bb1 = bv[col+1]; }
            else if (mode==3) { bb0 = bo[col]; bb1 = bo[col+1]; }
#pragma unroll
            for (int h=0;h<2;++h) {
                int m = m0 + rowb + h*8;
                float v0 = acc[mt][nt][h*2]   + bb0;
                float v1 = acc[mt][nt][h*2+1] + bb1;
                int b = m>>11, s = m&(NS-1);
                if (mode<=1) {
                    float2 cs = g_rope[s*32 + ((col&63)>>1)];
                    float a = v0, b2 = v1;
                    v0 = (a*cs.x - b2*cs.y)*ROT_SCALE;
                    v1 = (a*cs.y + b2*cs.x)*ROT_SCALE;
                }
                if (mode==3) {
                    *(float2*)(outp + (size_t)m*ND + col) = make_float2(v0, v1);
                } else {
                    int hh = col>>6, bh = b*NH + hh, d0 = col&63;
                    size_t off = ((size_t)bh*NS + s)*HD + d0;
                    uint32_t hi, lo;
                    split_pk(v0, v1, hi, lo);
                    __nv_bfloat16 *dh = (mode==0)?g_qh:(mode==1)?g_kh:g_vh;
                    __nv_bfloat16 *dl = (mode==0)?g_ql:(mode==1)?g_kl:g_vl;
                    *(uint32_t*)(dh+off) = hi;
                    *(uint32_t*)(dl+off) = lo;
                }
            }
        }
}

// ============================================================
// Attention: software-pipelined S/PV with ping-pong sacc buffers
// (kt unrolled by 2, no register copy) and V streamed in n-groups
// of 4 to stay under the spill threshold. 3 cp.async stages.
// ============================================================
#define A_KH 0
#define A_KL 9216
#define A_VH 18432
#define A_VL 27648
#define ASTG 36864
#define AS_SIZE (3*ASTG)   // 110592

__global__ __launch_bounds__(128, 2) void attn_tc(float* __restrict__ qk)
{
    extern __shared__ __align__(128) char sm[];
    const uint32_t smb = smem_u32(sm);
    const int t = threadIdx.x, lane = t&31, wm = t>>5;
    const int qt = (int)gridDim.x - 1 - (int)blockIdx.x;
    const int bh = blockIdx.y;
    const int i0 = qt*64;
    float* __restrict__ qkp = qk + (size_t)bh*NS*NS;

    const int lr = t>>3, lc8 = t&7;
    auto issue = [&](int kt){
        uint32_t sb = smb + (uint32_t)(kt%3)*ASTG;
#pragma unroll
        for (int i=0;i<4;++i) {
            int r = lr + i*16;
            uint32_t so = (uint32_t)(r*SMST + lc8*16);
            size_t go = ((size_t)bh*NS + kt*64 + r)*HD + lc8*8;
            cpa16(sb + A_KH + so, g_kh + go);
            cpa16(sb + A_KL + so, g_kl + go);
            cpa16(sb + A_VH + so, g_vh + go);
            cpa16(sb + A_VL + so, g_vl + go);
        }
        CPA_COMMIT();
    };

    // stage Q through stage-0 smem, grab fragments
#pragma unroll
    for (int i=0;i<4;++i) {
        int r = lr + i*16;
        uint32_t so = (uint32_t)(r*SMST + lc8*16);
        size_t go = ((size_t)bh*NS + i0 + r)*HD + lc8*8;
        *(uint4*)(sm + A_KH + so) = *(const uint4*)(g_qh + go);
        *(uint4*)(sm + A_KL + so) = *(const uint4*)(g_ql + go);
    }
    __syncthreads();
    uint32_t qfh[4][4], qfl[4][4];
#pragma unroll
    for (int kk=0;kk<4;++kk) {
        ldsm4(qfh[kk], addrA(smb + A_KH, wm*16, kk*16, lane));
        ldsm4(qfl[kk], addrA(smb + A_KL, wm*16, kk*16, lane));
    }
    __syncthreads();
    issue(0);
    if (qt >= 1) issue(1);

    float o[8][4];
#pragma unroll
    for (int n=0;n<8;++n)
#pragma unroll
        for (int q=0;q<4;++q) o[n][q] = 0.f;
    float l0 = 0.f, l1 = 0.f;

    const int r0 = lane>>2;
    const int irow0 = i0 + wm*16 + r0;
    const int irow1 = irow0 + 8;
    const int cql = (lane&3)<<1;

    float sA[8][4], sB[8][4];

    // ---- PV phase for tile kts (sacc already masked if needed) ----
    auto pv = [&](float (*sacc)[4], int kts, int gmax, int kmax2){
        uint32_t sb = smb + (uint32_t)(kts%3)*ASTG;
        float* qrow0 = qkp + (size_t)irow0*NS + kts*64 + cql;
        float* qrow1 = qkp + (size_t)irow1*NS + kts*64 + cql;
#pragma unroll
        for (int j=0;j<8;++j) {
            stg_cs2(qrow0 + j*8, sacc[j][0], sacc[j][1]);
            stg_cs2(qrow1 + j*8, sacc[j][2], sacc[j][3]);
        }
#pragma unroll
        for (int g=0; g<2; ++g) {
            if (g >= gmax) break;
            // exps + splits for both k16 subs of this k32 group
            uint32_t sh[2][4], sl[2][4];
            bool valid[2];
#pragma unroll
            for (int sub=0; sub<2; ++sub) {
                const int kk2 = g*2 + sub;
                valid[sub] = (kk2 < kmax2);
                if (valid[sub]) {
                    const int j0 = 2*kk2, j1 = j0+1;
                    float p00 = __expf(sacc[j0][0]), p01 = __expf(sacc[j0][1]);
                    float p02 = __expf(sacc[j0][2]), p03 = __expf(sacc[j0][3]);
                    float p10 = __expf(sacc[j1][0]), p11 = __expf(sacc[j1][1]);
                    float p12 = __expf(sacc[j1][2]), p13 = __expf(sacc[j1][3]);
                    l0 += (p00 + p01) + (p10 + p11);
                    l1 += (p02 + p03) + (p12 + p13);
                    split_pk(p00, p01, sh[sub][0], sl[sub][0]);
                    split_pk(p02, p03, sh[sub][1], sl[sub][1]);
                    split_pk(p10, p11, sh[sub][2], sl[sub][2]);
                    split_pk(p12, p13, sh[sub][3], sl[sub][3]);
                }
            }
            // stream V in n-groups of 4 (32 live V regs instead of 64)
#pragma unroll
            for (int ng=0; ng<2; ++ng) {
                uint32_t vh[4][4], vl[4][4];
#pragma unroll
                for (int n4=0;n4<4;++n4) {
                    ldsm4t(vh[n4], addrVt(sb+A_VH, g*32, (ng*4+n4)*8, lane));
                    ldsm4t(vl[n4], addrVt(sb+A_VL, g*32, (ng*4+n4)*8, lane));
                }
#pragma unroll
                for (int sub=0; sub<2; ++sub) {
                    if (!valid[sub]) continue;
#pragma unroll
                    for (int n4=0;n4<4;++n4)
                        mma16816v(o[ng*4+n4], sh[sub][0],sh[sub][1],sh[sub][2],sh[sub][3],
                                  vh[n4][sub*2], vh[n4][sub*2+1]);
#pragma unroll
                    for (int n4=0;n4<4;++n4)
                        mma16816v(o[ng*4+n4], sh[sub][0],sh[sub][1],sh[sub][2],sh[sub][3],
                                  vl[n4][sub*2], vl[n4][sub*2+1]);
#pragma unroll
                    for (int n4=0;n4<4;++n4)
                        mma16816v(o[ng*4+n4], sl[sub][0],sl[sub][1],sl[sub][2],sl[sub][3],
                                  vh[n4][sub*2], vh[n4][sub*2+1]);
                }
            }
        }
    };

    // ---- one pipelined iteration: S(kt)->dst overlapped with PV(kt-1)<-prev ----
    auto iter = [&](int kt, float (*dst)[4], float (*prev)[4]){
        if (kt < qt) { CPA_WAIT(1); } else { CPA_WAIT(0); }
        __syncthreads();
        uint32_t sb = smb + (uint32_t)(kt%3)*ASTG;
        const bool diag = (kt == qt);
        const int jmax = diag ? (2*wm + 2) : 8;
        const int tmax = diag ? (wm + 1)  : 4;

#pragma unroll
        for (int j=0;j<8;++j)
#pragma unroll
            for (int q=0;q<4;++q) dst[j][q] = -1e9f;
#pragma unroll
        for (int j=0;j<8;++j)
            if (j < jmax)
#pragma unroll
                for (int q=0;q<4;++q) dst[j][q] = 0.f;
#pragma unroll
        for (int kk=0;kk<4;++kk) {
            const int kb = kk*16;
            uint32_t kh16[16], kl16[16];
#pragma unroll
            for (int tn=0;tn<4;++tn) {
                if (tn < tmax) {
                    ldsm4(&kh16[tn*4], addrB(sb+A_KH, tn*16, kb, lane));
                    ldsm4(&kl16[tn*4], addrB(sb+A_KL, tn*16, kb, lane));
                }
            }
#pragma unroll
            for (int j=0;j<8;++j)
                if (j < jmax) mma16816(dst[j], qfh[kk], kh16[(j>>1)*4+(j&1)*2], kh16[(j>>1)*4+(j&1)*2+1]);
#pragma unroll
            for (int j=0;j<8;++j)
                if (j < jmax) mma16816(dst[j], qfh[kk], kl16[(j>>1)*4+(j&1)*2], kl16[(j>>1)*4+(j&1)*2+1]);
#pragma unroll
            for (int j=0;j<8;++j)
                if (j < jmax) mma16816(dst[j], qfl[kk], kh16[(j>>1)*4+(j&1)*2], kh16[(j>>1)*4+(j&1)*2+1]);
        }

        if (kt > 0) pv(prev, kt-1, 2, 4);   // overlapped with in-flight S-mmas

        __syncthreads();                    // stage (kt+2)%3 free after pv done
        if (kt+2 <= qt) issue(kt+2);
    };

    // ---- kt loop, unrolled by 2 with ping-pong buffers (no copy) ----
    for (int kt = 0; kt <= qt; kt += 2) {
        iter(kt, sA, sB);
        if (kt+1 <= qt) iter(kt+1, sB, sA);
    }

    // ---- epilogue: mask diagonal tile exactly, then PV ----
    {
        float (*slast)[4] = (qt & 1) ? sB : sA;
#pragma unroll
        for (int j=0;j<8;++j) {
            int jc = qt*64 + j*8 + cql;
            if (jc   > irow0) slast[j][0] = -1e9f;
            if (jc+1 > irow0) slast[j][1] = -1e9f;
            if (jc   > irow1) slast[j][2] = -1e9f;
            if (jc+1 > irow1) slast[j][3] = -1e9f;
        }
        pv(slast, qt, (wm>>1)+1, wm+1);
    }

    // ---- row sums + finalize ----
    l0 += __shfl_xor_sync(0xffffffffu, l0, 1);
    l0 += __shfl_xor_sync(0xffffffffu, l0, 2);
    l1 += __shfl_xor_sync(0xffffffffu, l1, 1);
    l1 += __shfl_xor_sync(0xffffffffu, l1, 2);
    const int b = bh>>4, hh = bh&15;
    const float li0 = 1.f / l0, li1 = 1.f / l1;
#pragma unroll
    for (int n=0;n<8;++n) {
        uint32_t hi, lo;
        float v0 = o[n][0]*li0, v1 = o[n][1]*li0;
        split_pk(v0, v1, hi, lo);
        size_t off0 = ((size_t)(b*NS + irow0))*ND + hh*HD + n*8 + cql;
        *(uint32_t*)(g_ah + off0) = hi;
        *(uint32_t*)(g_al + off0) = lo;
        float v2 = o[n][2]*li1, v3 = o[n][3]*li1;
        split_pk(v2, v3, hi, lo);
        size_t off1 = ((size_t)(b*NS + irow1))*ND + hh*HD + n*8 + cql;
        *(uint32_t*)(g_ah + off1) = hi;
        *(uint32_t*)(g_al + off1) = lo;
    }
}

// ---------------- launch ----------------
extern "C" void kernel_launch(void* const* d_in, const int* in_sizes, int n_in,
                              void* d_out, int out_size)
{
    const float* x    = (const float*)d_in[0];
    const float* Wq   = (const float*)d_in[2];
    const float* bq   = (const float*)d_in[3];
    const float* Wk   = (const float*)d_in[4];
    const float* Wv   = (const float*)d_in[5];
    const float* bv   = (const float*)d_in[6];
    const float* Wo   = (const float*)d_in[7];
    const float* bo   = (const float*)d_in[8];
    const float* invf = (const float*)d_in[9];

    float* out = (float*)d_out;
    float* qk  = out + (size_t)NM*ND;

    cudaFuncSetAttribute((const void*)gemm_tc, cudaFuncAttributeMaxDynamicSharedMemorySize, GS_SIZE);
    cudaFuncSetAttribute((const void*)attn_tc, cudaFuncAttributeMaxDynamicSharedMemorySize, AS_SIZE);

    prep_kernel<<<8192, 256>>>(x, Wq, Wk, Wv, Wo);
    rope_kernel<<<256, 256>>>(invf);
    gemm_tc<<<dim3(32,52), 128, GS_SIZE>>>(bq, bv, bo, nullptr, qk, 0);  // fill(y<4) + qkv
    attn_tc<<<dim3(32,32), 128, AS_SIZE>>>(qk);
    gemm_tc<<<dim3(32,16), 128, GS_SIZE>>>(bq, bv, bo, out, qk, 1);      // out proj
}

// round 12
// speedup vs baseline: 1.0028x; 1.0028x over previous
#include <cuda_runtime.h>
#include <cuda_bf16.h>
#include <math.h>
#include <stdint.h>

#define NB 2
#define NH 16
#define NS 2048
#define ND 1024
#define HD 64
#define NM (NB*NS)
#define ROT_SCALE 0.35355339059327378f

static __device__ __nv_bfloat16 g_xh[NM*ND], g_xl[NM*ND];
static __device__ __nv_bfloat16 g_wh[4*ND*ND], g_wl[4*ND*ND];
static __device__ __nv_bfloat16 g_qh[NM*ND], g_ql[NM*ND];   // [bh][s][64]
static __device__ __nv_bfloat16 g_kh[NM*ND], g_kl[NM*ND];
static __device__ __nv_bfloat16 g_vh[NM*ND], g_vl[NM*ND];
static __device__ __nv_bfloat16 g_ah[NM*ND], g_al[NM*ND];   // [m][1024]
static __device__ float2 g_rope[NS*32];

// ---------------- helpers ----------------
__device__ __forceinline__ uint32_t smem_u32(const void* p){
    uint32_t a; asm("{ .reg .u64 t; cvta.to.shared.u64 t, %1; cvt.u32.u64 %0, t; }":"=r"(a):"l"(p)); return a;
}
__device__ __forceinline__ void ldsm4(uint32_t* r, uint32_t a){
    asm volatile("ldmatrix.sync.aligned.m8n8.x4.shared.b16 {%0,%1,%2,%3}, [%4];"
        : "=r"(r[0]),"=r"(r[1]),"=r"(r[2]),"=r"(r[3]) : "r"(a));
}
__device__ __forceinline__ void ldsm4t(uint32_t* r, uint32_t a){
    asm volatile("ldmatrix.sync.aligned.m8n8.x4.trans.shared.b16 {%0,%1,%2,%3}, [%4];"
        : "=r"(r[0]),"=r"(r[1]),"=r"(r[2]),"=r"(r[3]) : "r"(a));
}
__device__ __forceinline__ void mma16816(float* c, const uint32_t* a, uint32_t b0, uint32_t b1){
    asm volatile("mma.sync.aligned.m16n8k16.row.col.f32.bf16.bf16.f32 "
        "{%0,%1,%2,%3}, {%4,%5,%6,%7}, {%8,%9}, {%0,%1,%2,%3};"
        : "+f"(c[0]),"+f"(c[1]),"+f"(c[2]),"+f"(c[3])
        : "r"(a[0]),"r"(a[1]),"r"(a[2]),"r"(a[3]), "r"(b0),"r"(b1));
}
__device__ __forceinline__ void mma16816v(float* c, uint32_t a0, uint32_t a1, uint32_t a2, uint32_t a3,
                                          uint32_t b0, uint32_t b1){
    asm volatile("mma.sync.aligned.m16n8k16.row.col.f32.bf16.bf16.f32 "
        "{%0,%1,%2,%3}, {%4,%5,%6,%7}, {%8,%9}, {%0,%1,%2,%3};"
        : "+f"(c[0]),"+f"(c[1]),"+f"(c[2]),"+f"(c[3])
        : "r"(a0),"r"(a1),"r"(a2),"r"(a3), "r"(b0),"r"(b1));
}
// hi = {bf16(b)|bf16(a)}, lo = residual pair; exact RN numerics
__device__ __forceinline__ void split_pk(float a, float b, uint32_t& hi, uint32_t& lo){
    uint32_t h; asm("cvt.rn.bf16x2.f32 %0, %1, %2;" : "=r"(h) : "f"(b), "f"(a));
    float ha = __uint_as_float(h << 16);
    float hb = __uint_as_float(h & 0xffff0000u);
    uint32_t l; asm("cvt.rn.bf16x2.f32 %0, %1, %2;" : "=r"(l) : "f"(b - hb), "f"(a - ha));
    hi = h; lo = l;
}
__device__ __forceinline__ void cpa16(uint32_t s, const void* g){
    asm volatile("cp.async.cg.shared.global [%0], [%1], 16;"::"r"(s),"l"(g));
}
#define CPA_COMMIT() asm volatile("cp.async.commit_group;" ::: "memory")
#define CPA_WAIT(n)  asm volatile("cp.async.wait_group %0;"::"n"(n):"memory")
__device__ __forceinline__ void stg_cs2(float* p, float a, float b){
    asm volatile("st.global.cs.v2.f32 [%0], {%1,%2};" :: "l"(p), "f"(a), "f"(b) : "memory");
}
__device__ __forceinline__ void stg_cs4(float* p, float4 v){
    asm volatile("st.global.cs.v4.f32 [%0], {%1,%2,%3,%4};"
        :: "l"(p), "f"(v.x), "f"(v.y), "f"(v.z), "f"(v.w) : "memory");
}

#define SMST 144
__device__ __forceinline__ uint32_t addrA(uint32_t base, int m, int k, int lane){
    int quad=lane>>3, rr=lane&7;
    return base + (uint32_t)((m + ((quad&1)<<3) + rr)*SMST + ((k + ((quad>>1)<<3))<<1));
}
__device__ __forceinline__ uint32_t addrB(uint32_t base, int n, int k, int lane){
    int quad=lane>>3, rr=lane&7;
    return base + (uint32_t)((n + ((quad>>1)<<3) + rr)*SMST + ((k + ((quad&1)<<3))<<1));
}
__device__ __forceinline__ uint32_t addrVt(uint32_t base, int k, int n, int lane){
    int quad=lane>>3, rr=lane&7;
    return base + (uint32_t)((k + (quad<<3) + rr)*SMST + (n<<1));
}

// ---------------- prep ----------------
__global__ __launch_bounds__(256) void prep_kernel(
    const float* __restrict__ x, const float* __restrict__ Wq,
    const float* __restrict__ Wk, const float* __restrict__ Wv,
    const float* __restrict__ Wo)
{
    size_t base = ((size_t)blockIdx.x*256 + threadIdx.x)*4;
    const float* src; __nv_bfloat16 *dh, *dl; size_t off;
    if (base < (size_t)NM*ND) { off = base; src = x + off; dh = g_xh; dl = g_xl; }
    else {
        off = base - (size_t)NM*ND;
        int ws = (int)(off >> 20);
        const float* W = (ws==0)?Wq:(ws==1)?Wk:(ws==2)?Wv:Wo;
        src = W + (off & 1048575u); dh = g_wh; dl = g_wl;
    }
    float4 v = *(const float4*)src;
    uint32_t h0,l0,h1,l1;
    split_pk(v.x,v.y,h0,l0); split_pk(v.z,v.w,h1,l1);
    *(uint32_t*)(dh+off)=h0; *(uint32_t*)(dh+off+2)=h1;
    *(uint32_t*)(dl+off)=l0; *(uint32_t*)(dl+off+2)=l1;
}

__global__ __launch_bounds__(256) void rope_kernel(const float* __restrict__ invf){
    int i = blockIdx.x*256 + threadIdx.x;
    int s = i >> 5, p = i & 31;
    float sn, cs; sincosf((float)s * invf[p], &sn, &cs);
    g_rope[i] = make_float2(cs, sn);
}

// ============================================================
// GEMM: C[128x128], 256 threads, 1 CTA/SM (8 warps), 2-stage
// cp.async, product-major mma. qkv launch: y<4 = fill blocks.
// ============================================================
#define G_AH 0
#define G_AL 18432
#define G_BH 36864
#define G_BL 55296
#define GSTG 73728
#define GS_SIZE (2*GSTG)   // 147456

__global__ __launch_bounds__(256, 1) void gemm_tc(
    const float* __restrict__ bq, const float* __restrict__ bv,
    const float* __restrict__ bo, float* __restrict__ outp,
    float* __restrict__ qk, int mode_base)
{
    if (mode_base==0 && blockIdx.y < 4) {
        int fid = (int)blockIdx.y*32 + (int)blockIdx.x;
        int bh = fid >> 2, part = fid & 3;
        float* qkp = qk + (size_t)bh*NS*NS;
        const float4 M9 = make_float4(-1e9f,-1e9f,-1e9f,-1e9f);
        for (int qt = part; qt < 31; qt += 4) {
            const int jstart = (qt+1)*64;
            const int n = NS - jstart;
            for (int r = qt*64; r < qt*64 + 64; ++r) {
                float* rp = qkp + (size_t)r*NS + jstart;
                for (int c = (int)threadIdx.x*4; c < n; c += 1024)
                    stg_cs4(rp + c, M9);
            }
        }
        return;
    }

    extern __shared__ __align__(128) char sm[];
    const uint32_t smb = smem_u32(sm);
    const int t = threadIdx.x, lane = t&31, wid = t>>5;
    const int wm = wid&3, wn = wid>>2;
    const int m0 = blockIdx.x*128;
    int mode, n0;
    if (mode_base==0) { int y = blockIdx.y-4; mode = y>>3; n0 = (y&7)*128; }
    else { mode = 3; n0 = blockIdx.y*128; }
    const __nv_bfloat16* Ah = (mode_base==0)? g_xh : g_ah;
    const __nv_bfloat16* Al = (mode_base==0)? g_xl : g_al;
    const __nv_bfloat16* Wh = g_wh + (size_t)mode*ND*ND;
    const __nv_bfloat16* Wl = g_wl + (size_t)mode*ND*ND;

    float acc[2][8][4];
#pragma unroll
    for (int i=0;i<2;++i)
#pragma unroll
        for (int j=0;j<8;++j)
#pragma unroll
            for (int q=0;q<4;++q) acc[i][j][q] = 0.f;

    const int lr = t>>3, lc8 = t&7;   // lr 0..31
    auto issue = [&](int chunk, int buf){
        const int k0 = chunk*64;
        uint32_t sb = smb + buf*GSTG;
#pragma unroll
        for (int i=0;i<4;++i) {
            int r = lr + i*32;
            uint32_t so = (uint32_t)(r*SMST + lc8*16);
            size_t ga = (size_t)(m0+r)*ND + k0 + lc8*8;
            size_t gw = (size_t)(n0+r)*ND + k0 + lc8*8;
            cpa16(sb + G_AH + so, Ah + ga);
            cpa16(sb + G_AL + so, Al + ga);
            cpa16(sb + G_BH + so, Wh + gw);
            cpa16(sb + G_BL + so, Wl + gw);
        }
        CPA_COMMIT();
    };

    issue(0, 0);
    for (int c = 0; c < 16; ++c) {
        CPA_WAIT(0);
        __syncthreads();
        if (c < 15) issue(c+1, (c+1)&1);
        uint32_t sb = smb + (c&1)*GSTG;
#pragma unroll
        for (int kk = 0; kk < 4; ++kk) {
            const int kb = kk*16;
            uint32_t ah[2][4], al[2][4], bh16[16], bl16[16];
#pragma unroll
            for (int mt=0;mt<2;++mt) {
                ldsm4(ah[mt], addrA(sb+G_AH, wm*32+mt*16, kb, lane));
                ldsm4(al[mt], addrA(sb+G_AL, wm*32+mt*16, kb, lane));
            }
#pragma unroll
            for (int tn=0;tn<4;++tn) {
                ldsm4(&bh16[tn*4], addrB(sb+G_BH, wn*64+tn*16, kb, lane));
                ldsm4(&bl16[tn*4], addrB(sb+G_BL, wn*64+tn*16, kb, lane));
            }
#pragma unroll
            for (int mt=0;mt<2;++mt)
#pragma unroll
                for (int nt=0;nt<8;++nt)
                    mma16816(acc[mt][nt], ah[mt], bh16[(nt>>1)*4+(nt&1)*2], bh16[(nt>>1)*4+(nt&1)*2+1]);
#pragma unroll
            for (int mt=0;mt<2;++mt)
#pragma unroll
                for (int nt=0;nt<8;++nt)
                    mma16816(acc[mt][nt], ah[mt], bl16[(nt>>1)*4+(nt&1)*2], bl16[(nt>>1)*4+(nt&1)*2+1]);
#pragma unroll
            for (int mt=0;mt<2;++mt)
#pragma unroll
                for (int nt=0;nt<8;++nt)
                    mma16816(acc[mt][nt], al[mt], bh16[(nt>>1)*4+(nt&1)*2], bh16[(nt>>1)*4+(nt&1)*2+1]);
        }
    }

    // ---- epilogue ----
#pragma unroll
    for (int mt=0;mt<2;++mt)
#pragma unroll
        for (int nt=0;nt<8;++nt) {
            int rowb = wm*32 + mt*16 + (lane>>2);
            int col  = n0 + wn*64 + nt*8 + ((lane&3)<<1);
            float bb0 = 0.f, bb1 = 0.f;
            if (mode==0)      { bb0 = bq[col]; bb1 = bq[col+1]; }
            else if (mode==2) { bb0 = bv[col]; bb1 = bv[col+1]; }
            else if (mode==3) { bb0 = bo[col]; bb1 = bo[col+1]; }
#pragma unroll
            for (int h=0;h<2;++h) {
                int m = m0 + rowb + h*8;
                float v0 = acc[mt][nt][h*2]   + bb0;
                float v1 = acc[mt][nt][h*2+1] + bb1;
                int b = m>>11, s = m&(NS-1);
                if (mode<=1) {
                    float2 cs = g_rope[s*32 + ((col&63)>>1)];
                    float a = v0, b2 = v1;
                    v0 = (a*cs.x - b2*cs.y)*ROT_SCALE;
                    v1 = (a*cs.y + b2*cs.x)*ROT_SCALE;
                }
                if (mode==3) {
                    *(float2*)(outp + (size_t)m*ND + col) = make_float2(v0, v1);
                } else {
                    int hh = col>>6, bh = b*NH + hh, d0 = col&63;
                    size_t off = ((size_t)bh*NS + s)*HD + d0;
                    uint32_t hi, lo;
                    split_pk(v0, v1, hi, lo);
                    __nv_bfloat16 *dh = (mode==0)?g_qh:(mode==1)?g_kh:g_vh;
                    __nv_bfloat16 *dl = (mode==0)?g_ql:(mode==1)?g_kl:g_vl;
                    *(uint32_t*)(dh+off) = hi;
                    *(uint32_t*)(dl+off) = lo;
                }
            }
        }
}

// ============================================================
// Attention: R10 version verbatim (software-pipelined S/PV,
// 3 cp.async stages, 128 threads, 2 CTAs/SM).
// ============================================================
#define A_KH 0
#define A_KL 9216
#define A_VH 18432
#define A_VL 27648
#define ASTG 36864
#define AS_SIZE (3*ASTG)   // 110592

__global__ __launch_bounds__(128, 2) void attn_tc(float* __restrict__ qk)
{
    extern __shared__ __align__(128) char sm[];
    const uint32_t smb = smem_u32(sm);
    const int t = threadIdx.x, lane = t&31, wm = t>>5;
    const int qt = (int)gridDim.x - 1 - (int)blockIdx.x;
    const int bh = blockIdx.y;
    const int i0 = qt*64;
    float* __restrict__ qkp = qk + (size_t)bh*NS*NS;

    const int lr = t>>3, lc8 = t&7;
    auto issue = [&](int kt){
        uint32_t sb = smb + (uint32_t)(kt%3)*ASTG;
#pragma unroll
        for (int i=0;i<4;++i) {
            int r = lr + i*16;
            uint32_t so = (uint32_t)(r*SMST + lc8*16);
            size_t go = ((size_t)bh*NS + kt*64 + r)*HD + lc8*8;
            cpa16(sb + A_KH + so, g_kh + go);
            cpa16(sb + A_KL + so, g_kl + go);
            cpa16(sb + A_VH + so, g_vh + go);
            cpa16(sb + A_VL + so, g_vl + go);
        }
        CPA_COMMIT();
    };

#pragma unroll
    for (int i=0;i<4;++i) {
        int r = lr + i*16;
        uint32_t so = (uint32_t)(r*SMST + lc8*16);
        size_t go = ((size_t)bh*NS + i0 + r)*HD + lc8*8;
        *(uint4*)(sm + A_KH + so) = *(const uint4*)(g_qh + go);
        *(uint4*)(sm + A_KL + so) = *(const uint4*)(g_ql + go);
    }
    __syncthreads();
    uint32_t qfh[4][4], qfl[4][4];
#pragma unroll
    for (int kk=0;kk<4;++kk) {
        ldsm4(qfh[kk], addrA(smb + A_KH, wm*16, kk*16, lane));
        ldsm4(qfl[kk], addrA(smb + A_KL, wm*16, kk*16, lane));
    }
    __syncthreads();
    issue(0);
    if (qt >= 1) issue(1);

    float o[8][4];
#pragma unroll
    for (int n=0;n<8;++n)
#pragma unroll
        for (int q=0;q<4;++q) o[n][q] = 0.f;
    float l0 = 0.f, l1 = 0.f;

    const int r0 = lane>>2;
    const int irow0 = i0 + wm*16 + r0;
    const int irow1 = irow0 + 8;
    const int cql = (lane&3)<<1;

    float sprev[8][4], scur[8][4];

    auto pv = [&](float (*sacc)[4], int kts, int gmax, int kmax2){
        uint32_t sb = smb + (uint32_t)(kts%3)*ASTG;
        float* qrow0 = qkp + (size_t)irow0*NS + kts*64 + cql;
        float* qrow1 = qkp + (size_t)irow1*NS + kts*64 + cql;
#pragma unroll
        for (int j=0;j<8;++j) {
            stg_cs2(qrow0 + j*8, sacc[j][0], sacc[j][1]);
            stg_cs2(qrow1 + j*8, sacc[j][2], sacc[j][3]);
        }
#pragma unroll
        for (int g=0; g<2; ++g) {
            if (g >= gmax) break;
            uint32_t vh[8][4], vl[8][4];
#pragma unroll
            for (int n=0;n<8;++n) {
                ldsm4t(vh[n], addrVt(sb+A_VH, g*32, n*8, lane));
                ldsm4t(vl[n], addrVt(sb+A_VL, g*32, n*8, lane));
            }
#pragma unroll
            for (int sub=0; sub<2; ++sub) {
                const int kk2 = g*2 + sub;
                if (kk2 >= kmax2) continue;
                const int j0 = 2*kk2, j1 = j0+1;
                float p00 = __expf(sacc[j0][0]), p01 = __expf(sacc[j0][1]);
                float p02 = __expf(sacc[j0][2]), p03 = __expf(sacc[j0][3]);
                float p10 = __expf(sacc[j1][0]), p11 = __expf(sacc[j1][1]);
                float p12 = __expf(sacc[j1][2]), p13 = __expf(sacc[j1][3]);
                l0 += (p00 + p01) + (p10 + p11);
                l1 += (p02 + p03) + (p12 + p13);
                uint32_t a0h,a0l,b0h,b0l,a1h,a1l,b1h,b1l;
                split_pk(p00, p01, a0h, a0l);
                split_pk(p02, p03, b0h, b0l);
                split_pk(p10, p11, a1h, a1l);
                split_pk(p12, p13, b1h, b1l);
#pragma unroll
                for (int n=0;n<8;++n)
                    mma16816v(o[n], a0h, b0h, a1h, b1h, vh[n][sub*2], vh[n][sub*2+1]);
#pragma unroll
                for (int n=0;n<8;++n)
                    mma16816v(o[n], a0h, b0h, a1h, b1h, vl[n][sub*2], vl[n][sub*2+1]);
#pragma unroll
                for (int n=0;n<8;++n)
                    mma16816v(o[n], a0l, b0l, a1l, b1l, vh[n][sub*2], vh[n][sub*2+1]);
            }
        }
    };

    for (int kt = 0; kt <= qt; ++kt) {
        if (kt < qt) { CPA_WAIT(1); } else { CPA_WAIT(0); }
        __syncthreads();
        uint32_t sb = smb + (uint32_t)(kt%3)*ASTG;
        const bool diag = (kt == qt);
        const int jmax = diag ? (2*wm + 2) : 8;
        const int tmax = diag ? (wm + 1)  : 4;

#pragma unroll
        for (int j=0;j<8;++j)
#pragma unroll
            for (int q=0;q<4;++q) scur[j][q] = -1e9f;
#pragma unroll
        for (int j=0;j<8;++j)
            if (j < jmax)
#pragma unroll
                for (int q=0;q<4;++q) scur[j][q] = 0.f;
#pragma unroll
        for (int kk=0;kk<4;++kk) {
            const int kb = kk*16;
            uint32_t kh16[16], kl16[16];
#pragma unroll
            for (int tn=0;tn<4;++tn) {
                if (tn < tmax) {
                    ldsm4(&kh16[tn*4], addrB(sb+A_KH, tn*16, kb, lane));
                    ldsm4(&kl16[tn*4], addrB(sb+A_KL, tn*16, kb, lane));
                }
            }
#pragma unroll
            for (int j=0;j<8;++j)
                if (j < jmax) mma16816(scur[j], qfh[kk], kh16[(j>>1)*4+(j&1)*2], kh16[(j>>1)*4+(j&1)*2+1]);
#pragma unroll
            for (int j=0;j<8;++j)
                if (j < jmax) mma16816(scur[j], qfh[kk], kl16[(j>>1)*4+(j&1)*2], kl16[(j>>1)*4+(j&1)*2+1]);
#pragma unroll
            for (int j=0;j<8;++j)
                if (j < jmax) mma16816(scur[j], qfl[kk], kh16[(j>>1)*4+(j&1)*2], kh16[(j>>1)*4+(j&1)*2+1]);
        }

        if (kt > 0) pv(sprev, kt-1, 2, 4);

        __syncthreads();
        if (kt+2 <= qt) issue(kt+2);

#pragma unroll
        for (int j=0;j<8;++j)
#pragma unroll
            for (int q=0;q<4;++q) sprev[j][q] = scur[j][q];
    }

    {
#pragma unroll
        for (int j=0;j<8;++j) {
            int jc = qt*64 + j*8 + cql;
            if (jc   > irow0) sprev[j][0] = -1e9f;
            if (jc+1 > irow0) sprev[j][1] = -1e9f;
            if (jc   > irow1) sprev[j][2] = -1e9f;
            if (jc+1 > irow1) sprev[j][3] = -1e9f;
        }
        pv(sprev, qt, (wm>>1)+1, wm+1);
    }

    l0 += __shfl_xor_sync(0xffffffffu, l0, 1);
    l0 += __shfl_xor_sync(0xffffffffu, l0, 2);
    l1 += __shfl_xor_sync(0xffffffffu, l1, 1);
    l1 += __shfl_xor_sync(0xffffffffu, l1, 2);
    const int b = bh>>4, hh = bh&15;
    const float li0 = 1.f / l0, li1 = 1.f / l1;
#pragma unroll
    for (int n=0;n<8;++n) {
        uint32_t hi, lo;
        float v0 = o[n][0]*li0, v1 = o[n][1]*li0;
        split_pk(v0, v1, hi, lo);
        size_t off0 = ((size_t)(b*NS + irow0))*ND + hh*HD + n*8 + cql;
        *(uint32_t*)(g_ah + off0) = hi;
        *(uint32_t*)(g_al + off0) = lo;
        float v2 = o[n][2]*li1, v3 = o[n][3]*li1;
        split_pk(v2, v3, hi, lo);
        size_t off1 = ((size_t)(b*NS + irow1))*ND + hh*HD + n*8 + cql;
        *(uint32_t*)(g_ah + off1) = hi;
        *(uint32_t*)(g_al + off1) = lo;
    }
}

// ---------------- launch ----------------
extern "C" void kernel_launch(void* const* d_in, const int* in_sizes, int n_in,
                              void* d_out, int out_size)
{
    const float* x    = (const float*)d_in[0];
    const float* Wq   = (const float*)d_in[2];
    const float* bq   = (const float*)d_in[3];
    const float* Wk   = (const float*)d_in[4];
    const float* Wv   = (const float*)d_in[5];
    const float* bv   = (const float*)d_in[6];
    const float* Wo   = (const float*)d_in[7];
    const float* bo   = (const float*)d_in[8];
    const float* invf = (const float*)d_in[9];

    float* out = (float*)d_out;
    float* qk  = out + (size_t)NM*ND;

    cudaFuncSetAttribute((const void*)gemm_tc, cudaFuncAttributeMaxDynamicSharedMemorySize, GS_SIZE);
    cudaFuncSetAttribute((const void*)attn_tc, cudaFuncAttributeMaxDynamicSharedMemorySize, AS_SIZE);

    prep_kernel<<<8192, 256>>>(x, Wq, Wk, Wv, Wo);
    rope_kernel<<<256, 256>>>(invf);
    gemm_tc<<<dim3(32,28), 256, GS_SIZE>>>(bq, bv, bo, nullptr, qk, 0);  // fill(y<4) + qkv
    attn_tc<<<dim3(32,32), 128, AS_SIZE>>>(qk);
    gemm_tc<<<dim3(32,8), 256, GS_SIZE>>>(bq, bv, bo, out, qk, 1);       // out proj
}

// round 13
// speedup vs baseline: 1.0141x; 1.0112x over previous
#include <cuda_runtime.h>
#include <cuda_bf16.h>
#include <math.h>
#include <stdint.h>

#define NB 2
#define NH 16
#define NS 2048
#define ND 1024
#define HD 64
#define NM (NB*NS)
#define ROT_SCALE 0.35355339059327378f

static __device__ __nv_bfloat16 g_xh[NM*ND], g_xl[NM*ND];
static __device__ __nv_bfloat16 g_wh[4*ND*ND], g_wl[4*ND*ND];
static __device__ __nv_bfloat16 g_qh[NM*ND], g_ql[NM*ND];   // [bh][s][64]
static __device__ __nv_bfloat16 g_kh[NM*ND], g_kl[NM*ND];
static __device__ __nv_bfloat16 g_vh[NM*ND], g_vl[NM*ND];
static __device__ __nv_bfloat16 g_ah[NM*ND], g_al[NM*ND];   // [m][1024]
static __device__ float2 g_rope[NS*32];

// ---------------- helpers ----------------
__device__ __forceinline__ uint32_t smem_u32(const void* p){
    uint32_t a; asm("{ .reg .u64 t; cvta.to.shared.u64 t, %1; cvt.u32.u64 %0, t; }":"=r"(a):"l"(p)); return a;
}
__device__ __forceinline__ void ldsm4(uint32_t* r, uint32_t a){
    asm volatile("ldmatrix.sync.aligned.m8n8.x4.shared.b16 {%0,%1,%2,%3}, [%4];"
        : "=r"(r[0]),"=r"(r[1]),"=r"(r[2]),"=r"(r[3]) : "r"(a));
}
__device__ __forceinline__ void ldsm4t(uint32_t* r, uint32_t a){
    asm volatile("ldmatrix.sync.aligned.m8n8.x4.trans.shared.b16 {%0,%1,%2,%3}, [%4];"
        : "=r"(r[0]),"=r"(r[1]),"=r"(r[2]),"=r"(r[3]) : "r"(a));
}
__device__ __forceinline__ void mma16816(float* c, const uint32_t* a, uint32_t b0, uint32_t b1){
    asm volatile("mma.sync.aligned.m16n8k16.row.col.f32.bf16.bf16.f32 "
        "{%0,%1,%2,%3}, {%4,%5,%6,%7}, {%8,%9}, {%0,%1,%2,%3};"
        : "+f"(c[0]),"+f"(c[1]),"+f"(c[2]),"+f"(c[3])
        : "r"(a[0]),"r"(a[1]),"r"(a[2]),"r"(a[3]), "r"(b0),"r"(b1));
}
__device__ __forceinline__ void mma16816v(float* c, uint32_t a0, uint32_t a1, uint32_t a2, uint32_t a3,
                                          uint32_t b0, uint32_t b1){
    asm volatile("mma.sync.aligned.m16n8k16.row.col.f32.bf16.bf16.f32 "
        "{%0,%1,%2,%3}, {%4,%5,%6,%7}, {%8,%9}, {%0,%1,%2,%3};"
        : "+f"(c[0]),"+f"(c[1]),"+f"(c[2]),"+f"(c[3])
        : "r"(a0),"r"(a1),"r"(a2),"r"(a3), "r"(b0),"r"(b1));
}
// hi = {bf16(b)|bf16(a)}, lo = residual pair; exact RN numerics
__device__ __forceinline__ void split_pk(float a, float b, uint32_t& hi, uint32_t& lo){
    uint32_t h; asm("cvt.rn.bf16x2.f32 %0, %1, %2;" : "=r"(h) : "f"(b), "f"(a));
    float ha = __uint_as_float(h << 16);
    float hb = __uint_as_float(h & 0xffff0000u);
    uint32_t l; asm("cvt.rn.bf16x2.f32 %0, %1, %2;" : "=r"(l) : "f"(b - hb), "f"(a - ha));
    hi = h; lo = l;
}
__device__ __forceinline__ void cpa16(uint32_t s, const void* g){
    asm volatile("cp.async.cg.shared.global [%0], [%1], 16;"::"r"(s),"l"(g));
}
#define CPA_COMMIT() asm volatile("cp.async.commit_group;" ::: "memory")
#define CPA_WAIT(n)  asm volatile("cp.async.wait_group %0;"::"n"(n):"memory")
__device__ __forceinline__ void stg_cs2(float* p, float a, float b){
    asm volatile("st.global.cs.v2.f32 [%0], {%1,%2};" :: "l"(p), "f"(a), "f"(b) : "memory");
}
__device__ __forceinline__ void stg_cs4(float* p, float4 v){
    asm volatile("st.global.cs.v4.f32 [%0], {%1,%2,%3,%4};"
        :: "l"(p), "f"(v.x), "f"(v.y), "f"(v.z), "f"(v.w) : "memory");
}

#define SMST 144
__device__ __forceinline__ uint32_t addrA(uint32_t base, int m, int k, int lane){
    int quad=lane>>3, rr=lane&7;
    return base + (uint32_t)((m + ((quad&1)<<3) + rr)*SMST + ((k + ((quad>>1)<<3))<<1));
}
__device__ __forceinline__ uint32_t addrB(uint32_t base, int n, int k, int lane){
    int quad=lane>>3, rr=lane&7;
    return base + (uint32_t)((n + ((quad>>1)<<3) + rr)*SMST + ((k + ((quad&1)<<3))<<1));
}
__device__ __forceinline__ uint32_t addrVt(uint32_t base, int k, int n, int lane){
    int quad=lane>>3, rr=lane&7;
    return base + (uint32_t)((k + (quad<<3) + rr)*SMST + (n<<1));
}

// ---------------- prep ----------------
__global__ __launch_bounds__(256) void prep_kernel(
    const float* __restrict__ x, const float* __restrict__ Wq,
    const float* __restrict__ Wk, const float* __restrict__ Wv,
    const float* __restrict__ Wo)
{
    size_t base = ((size_t)blockIdx.x*256 + threadIdx.x)*4;
    const float* src; __nv_bfloat16 *dh, *dl; size_t off;
    if (base < (size_t)NM*ND) { off = base; src = x + off; dh = g_xh; dl = g_xl; }
    else {
        off = base - (size_t)NM*ND;
        int ws = (int)(off >> 20);
        const float* W = (ws==0)?Wq:(ws==1)?Wk:(ws==2)?Wv:Wo;
        src = W + (off & 1048575u); dh = g_wh; dl = g_wl;
    }
    float4 v = *(const float4*)src;
    uint32_t h0,l0,h1,l1;
    split_pk(v.x,v.y,h0,l0); split_pk(v.z,v.w,h1,l1);
    *(uint32_t*)(dh+off)=h0; *(uint32_t*)(dh+off+2)=h1;
    *(uint32_t*)(dl+off)=l0; *(uint32_t*)(dl+off+2)=l1;
}

__global__ __launch_bounds__(256) void rope_kernel(const float* __restrict__ invf){
    int i = blockIdx.x*256 + threadIdx.x;
    int s = i >> 5, p = i & 31;
    float sn, cs; sincosf((float)s * invf[p], &sn, &cs);
    g_rope[i] = make_float2(cs, sn);
}

// ============================================================
// GEMM: C[128x64], 128 threads, 2 CTAs/SM (R10 version verbatim).
// qkv launch: blockIdx.y<4 = fill blocks (run first, overlap waves).
// ============================================================
#define G_AH 0
#define G_AL 18432
#define G_BH 36864
#define G_BL 46080
#define GSTG 55296
#define GS_SIZE (2*GSTG)

__global__ __launch_bounds__(128, 2) void gemm_tc(
    const float* __restrict__ bq, const float* __restrict__ bv,
    const float* __restrict__ bo, float* __restrict__ outp,
    float* __restrict__ qk, int mode_base)
{
    if (mode_base==0 && blockIdx.y < 4) {
        int fid = (int)blockIdx.y*32 + (int)blockIdx.x;
        int bh = fid >> 2, part = fid & 3;
        float* qkp = qk + (size_t)bh*NS*NS;
        const float4 M9 = make_float4(-1e9f,-1e9f,-1e9f,-1e9f);
        for (int qt = part; qt < 31; qt += 4) {
            const int jstart = (qt+1)*64;
            const int n = NS - jstart;
            for (int r = qt*64; r < qt*64 + 64; ++r) {
                float* rp = qkp + (size_t)r*NS + jstart;
                for (int c = (int)threadIdx.x*4; c < n; c += 512)
                    stg_cs4(rp + c, M9);
            }
        }
        return;
    }

    extern __shared__ __align__(128) char sm[];
    const uint32_t smb = smem_u32(sm);
    const int t = threadIdx.x, lane = t&31, wm = t>>5;
    const int m0 = blockIdx.x*128;
    int mode, n0;
    if (mode_base==0) { int y = blockIdx.y-4; mode = y>>4; n0 = (y&15)*64; }
    else { mode = 3; n0 = blockIdx.y*64; }
    const __nv_bfloat16* Ah = (mode_base==0)? g_xh : g_ah;
    const __nv_bfloat16* Al = (mode_base==0)? g_xl : g_al;
    const __nv_bfloat16* Wh = g_wh + (size_t)mode*ND*ND;
    const __nv_bfloat16* Wl = g_wl + (size_t)mode*ND*ND;

    float acc[2][8][4];
#pragma unroll
    for (int i=0;i<2;++i)
#pragma unroll
        for (int j=0;j<8;++j)
#pragma unroll
            for (int q=0;q<4;++q) acc[i][j][q] = 0.f;

    const int lr = t>>3, lc8 = t&7;
    auto issue = [&](int chunk, int buf){
        const int k0 = chunk*64;
        uint32_t sb = smb + buf*GSTG;
#pragma unroll
        for (int i=0;i<8;++i) {
            int r = lr + i*16;
            uint32_t so = (uint32_t)(r*SMST + lc8*16);
            size_t ga = (size_t)(m0+r)*ND + k0 + lc8*8;
            cpa16(sb + G_AH + so, Ah + ga);
            cpa16(sb + G_AL + so, Al + ga);
        }
#pragma unroll
        for (int i=0;i<4;++i) {
            int r = lr + i*16;
            uint32_t so = (uint32_t)(r*SMST + lc8*16);
            size_t gw = (size_t)(n0+r)*ND + k0 + lc8*8;
            cpa16(sb + G_BH + so, Wh + gw);
            cpa16(sb + G_BL + so, Wl + gw);
        }
        CPA_COMMIT();
    };

    issue(0, 0);
    for (int c = 0; c < 16; ++c) {
        CPA_WAIT(0);
        __syncthreads();
        if (c < 15) issue(c+1, (c+1)&1);
        uint32_t sb = smb + (c&1)*GSTG;
#pragma unroll
        for (int kk = 0; kk < 4; ++kk) {
            const int kb = kk*16;
            uint32_t ah[2][4], al[2][4], bh16[16], bl16[16];
#pragma unroll
            for (int mt=0;mt<2;++mt) {
                ldsm4(ah[mt], addrA(sb+G_AH, wm*32+mt*16, kb, lane));
                ldsm4(al[mt], addrA(sb+G_AL, wm*32+mt*16, kb, lane));
            }
#pragma unroll
            for (int tn=0;tn<4;++tn) {
                ldsm4(&bh16[tn*4], addrB(sb+G_BH, tn*16, kb, lane));
                ldsm4(&bl16[tn*4], addrB(sb+G_BL, tn*16, kb, lane));
            }
#pragma unroll
            for (int mt=0;mt<2;++mt)
#pragma unroll
                for (int nt=0;nt<8;++nt)
                    mma16816(acc[mt][nt], ah[mt], bh16[(nt>>1)*4+(nt&1)*2], bh16[(nt>>1)*4+(nt&1)*2+1]);
#pragma unroll
            for (int mt=0;mt<2;++mt)
#pragma unroll
                for (int nt=0;nt<8;++nt)
                    mma16816(acc[mt][nt], ah[mt], bl16[(nt>>1)*4+(nt&1)*2], bl16[(nt>>1)*4+(nt&1)*2+1]);
#pragma unroll
            for (int mt=0;mt<2;++mt)
#pragma unroll
                for (int nt=0;nt<8;++nt)
                    mma16816(acc[mt][nt], al[mt], bh16[(nt>>1)*4+(nt&1)*2], bh16[(nt>>1)*4+(nt&1)*2+1]);
        }
    }

#pragma unroll
    for (int mt=0;mt<2;++mt)
#pragma unroll
        for (int nt=0;nt<8;++nt) {
            int rowb = wm*32 + mt*16 + (lane>>2);
            int col  = n0 + nt*8 + ((lane&3)<<1);
            float bb0 = 0.f, bb1 = 0.f;
            if (mode==0)      { bb0 = bq[col]; bb1 = bq[col+1]; }
            else if (mode==2) { bb0 = bv[col]; bb1 = bv[col+1]; }
            else if (mode==3) { bb0 = bo[col]; bb1 = bo[col+1]; }
#pragma unroll
            for (int h=0;h<2;++h) {
                int m = m0 + rowb + h*8;
                float v0 = acc[mt][nt][h*2]   + bb0;
                float v1 = acc[mt][nt][h*2+1] + bb1;
                int b = m>>11, s = m&(NS-1);
                if (mode<=1) {
                    float2 cs = g_rope[s*32 + ((col&63)>>1)];
                    float a = v0, b2 = v1;
                    v0 = (a*cs.x - b2*cs.y)*ROT_SCALE;
                    v1 = (a*cs.y + b2*cs.x)*ROT_SCALE;
                }
                if (mode==3) {
                    *(float2*)(outp + (size_t)m*ND + col) = make_float2(v0, v1);
                } else {
                    int hh = col>>6, bh = b*NH + hh, d0 = col&63;
                    size_t off = ((size_t)bh*NS + s)*HD + d0;
                    uint32_t hi, lo;
                    split_pk(v0, v1, hi, lo);
                    __nv_bfloat16 *dh = (mode==0)?g_qh:(mode==1)?g_kh:g_vh;
                    __nv_bfloat16 *dl = (mode==0)?g_ql:(mode==1)?g_kl:g_vl;
                    *(uint32_t*)(dh+off) = hi;
                    *(uint32_t*)(dl+off) = lo;
                }
            }
        }
}

// ============================================================
// Attention: R10 pipeline, kt unrolled x2 via MACRO (direct-named
// S accumulators, no copy, no pointer writes), V streamed in
// n-groups of 4 inside pv (peak regs down ~32).
// ============================================================
#define A_KH 0
#define A_KL 9216
#define A_VH 18432
#define A_VL 27648
#define ASTG 36864
#define AS_SIZE (3*ASTG)   // 110592

__global__ __launch_bounds__(128, 2) void attn_tc(float* __restrict__ qk)
{
    extern __shared__ __align__(128) char sm[];
    const uint32_t smb = smem_u32(sm);
    const int t = threadIdx.x, lane = t&31, wm = t>>5;
    const int qt = (int)gridDim.x - 1 - (int)blockIdx.x;
    const int bh = blockIdx.y;
    const int i0 = qt*64;
    float* __restrict__ qkp = qk + (size_t)bh*NS*NS;

    const int lr = t>>3, lc8 = t&7;
    auto issue = [&](int kt){
        uint32_t sb = smb + (uint32_t)(kt%3)*ASTG;
#pragma unroll
        for (int i=0;i<4;++i) {
            int r = lr + i*16;
            uint32_t so = (uint32_t)(r*SMST + lc8*16);
            size_t go = ((size_t)bh*NS + kt*64 + r)*HD + lc8*8;
            cpa16(sb + A_KH + so, g_kh + go);
            cpa16(sb + A_KL + so, g_kl + go);
            cpa16(sb + A_VH + so, g_vh + go);
            cpa16(sb + A_VL + so, g_vl + go);
        }
        CPA_COMMIT();
    };

#pragma unroll
    for (int i=0;i<4;++i) {
        int r = lr + i*16;
        uint32_t so = (uint32_t)(r*SMST + lc8*16);
        size_t go = ((size_t)bh*NS + i0 + r)*HD + lc8*8;
        *(uint4*)(sm + A_KH + so) = *(const uint4*)(g_qh + go);
        *(uint4*)(sm + A_KL + so) = *(const uint4*)(g_ql + go);
    }
    __syncthreads();
    uint32_t qfh[4][4], qfl[4][4];
#pragma unroll
    for (int kk=0;kk<4;++kk) {
        ldsm4(qfh[kk], addrA(smb + A_KH, wm*16, kk*16, lane));
        ldsm4(qfl[kk], addrA(smb + A_KL, wm*16, kk*16, lane));
    }
    __syncthreads();
    issue(0);
    if (qt >= 1) issue(1);

    float o[8][4];
#pragma unroll
    for (int n=0;n<8;++n)
#pragma unroll
        for (int q=0;q<4;++q) o[n][q] = 0.f;
    float l0 = 0.f, l1 = 0.f;

    const int r0 = lane>>2;
    const int irow0 = i0 + wm*16 + r0;
    const int irow1 = irow0 + 8;
    const int cql = (lane&3)<<1;

    float sA[8][4], sB[8][4];

    // PV: read-only sacc pointer (safe per R10); V streamed in n-groups of 4
    auto pv = [&](const float (*sacc)[4], int kts, int gmax, int kmax2){
        uint32_t sb = smb + (uint32_t)(kts%3)*ASTG;
        float* qrow0 = qkp + (size_t)irow0*NS + kts*64 + cql;
        float* qrow1 = qkp + (size_t)irow1*NS + kts*64 + cql;
#pragma unroll
        for (int j=0;j<8;++j) {
            stg_cs2(qrow0 + j*8, sacc[j][0], sacc[j][1]);
            stg_cs2(qrow1 + j*8, sacc[j][2], sacc[j][3]);
        }
#pragma unroll
        for (int g=0; g<2; ++g) {
            if (g >= gmax) break;
            uint32_t sh[2][4], sl[2][4];
#pragma unroll
            for (int sub=0; sub<2; ++sub) {
                if (g*2+sub < kmax2) {
                    const int j0 = 2*(g*2+sub), j1 = j0+1;
                    float p00 = __expf(sacc[j0][0]), p01 = __expf(sacc[j0][1]);
                    float p02 = __expf(sacc[j0][2]), p03 = __expf(sacc[j0][3]);
                    float p10 = __expf(sacc[j1][0]), p11 = __expf(sacc[j1][1]);
                    float p12 = __expf(sacc[j1][2]), p13 = __expf(sacc[j1][3]);
                    l0 += (p00 + p01) + (p10 + p11);
                    l1 += (p02 + p03) + (p12 + p13);
                    split_pk(p00, p01, sh[sub][0], sl[sub][0]);
                    split_pk(p02, p03, sh[sub][1], sl[sub][1]);
                    split_pk(p10, p11, sh[sub][2], sl[sub][2]);
                    split_pk(p12, p13, sh[sub][3], sl[sub][3]);
                }
            }
#pragma unroll
            for (int ng=0; ng<2; ++ng) {
                uint32_t vh[4][4], vl[4][4];
#pragma unroll
                for (int n4=0;n4<4;++n4) {
                    ldsm4t(vh[n4], addrVt(sb+A_VH, g*32, (ng*4+n4)*8, lane));
                    ldsm4t(vl[n4], addrVt(sb+A_VL, g*32, (ng*4+n4)*8, lane));
                }
#pragma unroll
                for (int sub=0; sub<2; ++sub) {
                    if (g*2+sub >= kmax2) continue;
#pragma unroll
                    for (int n4=0;n4<4;++n4)
                        mma16816v(o[ng*4+n4], sh[sub][0],sh[sub][1],sh[sub][2],sh[sub][3],
                                  vh[n4][sub*2], vh[n4][sub*2+1]);
#pragma unroll
                    for (int n4=0;n4<4;++n4)
                        mma16816v(o[ng*4+n4], sh[sub][0],sh[sub][1],sh[sub][2],sh[sub][3],
                                  vl[n4][sub*2], vl[n4][sub*2+1]);
#pragma unroll
                    for (int n4=0;n4<4;++n4)
                        mma16816v(o[ng*4+n4], sl[sub][0],sl[sub][1],sl[sub][2],sl[sub][3],
                                  vh[n4][sub*2], vh[n4][sub*2+1]);
                }
            }
        }
    };

// one pipelined iteration; SCUR/SPREV are literal array names (direct regs)
#define ATTN_ITER(KT, SCUR, SPREV) do { \
    if ((KT) < qt) { CPA_WAIT(1); } else { CPA_WAIT(0); } \
    __syncthreads(); \
    uint32_t sb_ = smb + (uint32_t)((KT)%3)*ASTG; \
    const bool diag_ = ((KT) == qt); \
    const int jmax_ = diag_ ? (2*wm + 2) : 8; \
    const int tmax_ = diag_ ? (wm + 1) : 4; \
    _Pragma("unroll") for (int j=0;j<8;++j) \
        _Pragma("unroll") for (int q=0;q<4;++q) SCUR[j][q] = (j < jmax_) ? 0.f : -1e9f; \
    _Pragma("unroll") for (int kk=0;kk<4;++kk) { \
        const int kb_ = kk*16; \
        uint32_t kh16[16], kl16[16]; \
        _Pragma("unroll") for (int tn=0;tn<4;++tn) { \
            if (tn < tmax_) { \
                ldsm4(&kh16[tn*4], addrB(sb_+A_KH, tn*16, kb_, lane)); \
                ldsm4(&kl16[tn*4], addrB(sb_+A_KL, tn*16, kb_, lane)); \
            } \
        } \
        _Pragma("unroll") for (int j=0;j<8;++j) \
            if (j < jmax_) mma16816(SCUR[j], qfh[kk], kh16[(j>>1)*4+(j&1)*2], kh16[(j>>1)*4+(j&1)*2+1]); \
        _Pragma("unroll") for (int j=0;j<8;++j) \
            if (j < jmax_) mma16816(SCUR[j], qfh[kk], kl16[(j>>1)*4+(j&1)*2], kl16[(j>>1)*4+(j&1)*2+1]); \
        _Pragma("unroll") for (int j=0;j<8;++j) \
            if (j < jmax_) mma16816(SCUR[j], qfl[kk], kh16[(j>>1)*4+(j&1)*2], kh16[(j>>1)*4+(j&1)*2+1]); \
    } \
    if ((KT) > 0) pv(SPREV, (KT)-1, 2, 4); \
    __syncthreads(); \
    if ((KT)+2 <= qt) issue((KT)+2); \
} while(0)

    for (int kt = 0; kt <= qt; kt += 2) {
        ATTN_ITER(kt, sA, sB);
        if (kt+1 <= qt) ATTN_ITER(kt+1, sB, sA);
    }

    // epilogue: mask diagonal tile exactly, then PV (direct-named arrays)
    if (qt & 1) {
#pragma unroll
        for (int j=0;j<8;++j) {
            int jc = qt*64 + j*8 + cql;
            if (jc   > irow0) sB[j][0] = -1e9f;
            if (jc+1 > irow0) sB[j][1] = -1e9f;
            if (jc   > irow1) sB[j][2] = -1e9f;
            if (jc+1 > irow1) sB[j][3] = -1e9f;
        }
        pv(sB, qt, (wm>>1)+1, wm+1);
    } else {
#pragma unroll
        for (int j=0;j<8;++j) {
            int jc = qt*64 + j*8 + cql;
            if (jc   > irow0) sA[j][0] = -1e9f;
            if (jc+1 > irow0) sA[j][1] = -1e9f;
            if (jc   > irow1) sA[j][2] = -1e9f;
            if (jc+1 > irow1) sA[j][3] = -1e9f;
        }
        pv(sA, qt, (wm>>1)+1, wm+1);
    }

    // row sums + finalize
    l0 += __shfl_xor_sync(0xffffffffu, l0, 1);
    l0 += __shfl_xor_sync(0xffffffffu, l0, 2);
    l1 += __shfl_xor_sync(0xffffffffu, l1, 1);
    l1 += __shfl_xor_sync(0xffffffffu, l1, 2);
    const int b = bh>>4, hh = bh&15;
    const float li0 = 1.f / l0, li1 = 1.f / l1;
#pragma unroll
    for (int n=0;n<8;++n) {
        uint32_t hi, lo;
        float v0 = o[n][0]*li0, v1 = o[n][1]*li0;
        split_pk(v0, v1, hi, lo);
        size_t off0 = ((size_t)(b*NS + irow0))*ND + hh*HD + n*8 + cql;
        *(uint32_t*)(g_ah + off0) = hi;
        *(uint32_t*)(g_al + off0) = lo;
        float v2 = o[n][2]*li1, v3 = o[n][3]*li1;
        split_pk(v2, v3, hi, lo);
        size_t off1 = ((size_t)(b*NS + irow1))*ND + hh*HD + n*8 + cql;
        *(uint32_t*)(g_ah + off1) = hi;
        *(uint32_t*)(g_al + off1) = lo;
    }
}

// ---------------- launch ----------------
extern "C" void kernel_launch(void* const* d_in, const int* in_sizes, int n_in,
                              void* d_out, int out_size)
{
    const float* x    = (const float*)d_in[0];
    const float* Wq   = (const float*)d_in[2];
    const float* bq   = (const float*)d_in[3];
    const float* Wk   = (const float*)d_in[4];
    const float* Wv   = (const float*)d_in[5];
    const float* bv   = (const float*)d_in[6];
    const float* Wo   = (const float*)d_in[7];
    const float* bo   = (const float*)d_in[8];
    const float* invf = (const float*)d_in[9];

    float* out = (float*)d_out;
    float* qk  = out + (size_t)NM*ND;

    cudaFuncSetAttribute((const void*)gemm_tc, cudaFuncAttributeMaxDynamicSharedMemorySize, GS_SIZE);
    cudaFuncSetAttribute((const void*)attn_tc, cudaFuncAttributeMaxDynamicSharedMemorySize, AS_SIZE);

    prep_kernel<<<8192, 256>>>(x, Wq, Wk, Wv, Wo);
    rope_kernel<<<256, 256>>>(invf);
    gemm_tc<<<dim3(32,52), 128, GS_SIZE>>>(bq, bv, bo, nullptr, qk, 0);  // fill(y<4) + qkv
    attn_tc<<<dim3(32,32), 128, AS_SIZE>>>(qk);
    gemm_tc<<<dim3(32,16), 128, GS_SIZE>>>(bq, bv, bo, out, qk, 1);      // out proj
}

// round 14
// speedup vs baseline: 1.0535x; 1.0389x over previous
#include <cuda_runtime.h>
#include <cuda_bf16.h>
#include <math.h>
#include <stdint.h>

#define NB 2
#define NH 16
#define NS 2048
#define ND 1024
#define HD 64
#define NM (NB*NS)
#define ROT_SCALE 0.35355339059327378f

static __device__ __nv_bfloat16 g_xh[NM*ND], g_xl[NM*ND];
static __device__ __nv_bfloat16 g_wh[4*ND*ND], g_wl[4*ND*ND];
static __device__ __nv_bfloat16 g_qh[NM*ND], g_ql[NM*ND];   // [bh][s][64]
static __device__ __nv_bfloat16 g_kh[NM*ND], g_kl[NM*ND];
static __device__ __nv_bfloat16 g_vh[NM*ND], g_vl[NM*ND];
static __device__ __nv_bfloat16 g_ah[NM*ND], g_al[NM*ND];   // [m][1024]
static __device__ float2 g_rope[NS*32];

// ---------------- helpers ----------------
__device__ __forceinline__ uint32_t smem_u32(const void* p){
    uint32_t a; asm("{ .reg .u64 t; cvta.to.shared.u64 t, %1; cvt.u32.u64 %0, t; }":"=r"(a):"l"(p)); return a;
}
__device__ __forceinline__ void ldsm4(uint32_t* r, uint32_t a){
    asm volatile("ldmatrix.sync.aligned.m8n8.x4.shared.b16 {%0,%1,%2,%3}, [%4];"
        : "=r"(r[0]),"=r"(r[1]),"=r"(r[2]),"=r"(r[3]) : "r"(a));
}
__device__ __forceinline__ void ldsm4t(uint32_t* r, uint32_t a){
    asm volatile("ldmatrix.sync.aligned.m8n8.x4.trans.shared.b16 {%0,%1,%2,%3}, [%4];"
        : "=r"(r[0]),"=r"(r[1]),"=r"(r[2]),"=r"(r[3]) : "r"(a));
}
__device__ __forceinline__ void mma16816(float* c, const uint32_t* a, uint32_t b0, uint32_t b1){
    asm volatile("mma.sync.aligned.m16n8k16.row.col.f32.bf16.bf16.f32 "
        "{%0,%1,%2,%3}, {%4,%5,%6,%7}, {%8,%9}, {%0,%1,%2,%3};"
        : "+f"(c[0]),"+f"(c[1]),"+f"(c[2]),"+f"(c[3])
        : "r"(a[0]),"r"(a[1]),"r"(a[2]),"r"(a[3]), "r"(b0),"r"(b1));
}
__device__ __forceinline__ void mma16816v(float* c, uint32_t a0, uint32_t a1, uint32_t a2, uint32_t a3,
                                          uint32_t b0, uint32_t b1){
    asm volatile("mma.sync.aligned.m16n8k16.row.col.f32.bf16.bf16.f32 "
        "{%0,%1,%2,%3}, {%4,%5,%6,%7}, {%8,%9}, {%0,%1,%2,%3};"
        : "+f"(c[0]),"+f"(c[1]),"+f"(c[2]),"+f"(c[3])
        : "r"(a0),"r"(a1),"r"(a2),"r"(a3), "r"(b0),"r"(b1));
}
// hi = {bf16(b)|bf16(a)}, lo = residual pair; exact RN numerics
__device__ __forceinline__ void split_pk(float a, float b, uint32_t& hi, uint32_t& lo){
    uint32_t h; asm("cvt.rn.bf16x2.f32 %0, %1, %2;" : "=r"(h) : "f"(b), "f"(a));
    float ha = __uint_as_float(h << 16);
    float hb = __uint_as_float(h & 0xffff0000u);
    uint32_t l; asm("cvt.rn.bf16x2.f32 %0, %1, %2;" : "=r"(l) : "f"(b - hb), "f"(a - ha));
    hi = h; lo = l;
}
__device__ __forceinline__ void cpa16(uint32_t s, const void* g){
    asm volatile("cp.async.cg.shared.global [%0], [%1], 16;"::"r"(s),"l"(g));
}
#define CPA_COMMIT() asm volatile("cp.async.commit_group;" ::: "memory")
#define CPA_WAIT(n)  asm volatile("cp.async.wait_group %0;"::"n"(n):"memory")
__device__ __forceinline__ void stg_cs2(float* p, float a, float b){
    asm volatile("st.global.cs.v2.f32 [%0], {%1,%2};" :: "l"(p), "f"(a), "f"(b) : "memory");
}
__device__ __forceinline__ void stg_cs4(float* p, float4 v){
    asm volatile("st.global.cs.v4.f32 [%0], {%1,%2,%3,%4};"
        :: "l"(p), "f"(v.x), "f"(v.y), "f"(v.z), "f"(v.w) : "memory");
}

#define SMST 144   // attn smem row stride (64 bf16 + pad)
#define GST2 80    // gemm smem row stride (32 bf16 + pad)
__device__ __forceinline__ uint32_t addrA(uint32_t base, int m, int k, int lane, int strideB){
    int quad=lane>>3, rr=lane&7;
    return base + (uint32_t)((m + ((quad&1)<<3) + rr)*strideB + ((k + ((quad>>1)<<3))<<1));
}
__device__ __forceinline__ uint32_t addrB(uint32_t base, int n, int k, int lane, int strideB){
    int quad=lane>>3, rr=lane&7;
    return base + (uint32_t)((n + ((quad>>1)<<3) + rr)*strideB + ((k + ((quad&1)<<3))<<1));
}
__device__ __forceinline__ uint32_t addrVt(uint32_t base, int k, int n, int lane, int strideB){
    int quad=lane>>3, rr=lane&7;
    return base + (uint32_t)((k + (quad<<3) + rr)*strideB + (n<<1));
}

// ---------------- prep ----------------
__global__ __launch_bounds__(256) void prep_kernel(
    const float* __restrict__ x, const float* __restrict__ Wq,
    const float* __restrict__ Wk, const float* __restrict__ Wv,
    const float* __restrict__ Wo)
{
    size_t base = ((size_t)blockIdx.x*256 + threadIdx.x)*4;
    const float* src; __nv_bfloat16 *dh, *dl; size_t off;
    if (base < (size_t)NM*ND) { off = base; src = x + off; dh = g_xh; dl = g_xl; }
    else {
        off = base - (size_t)NM*ND;
        int ws = (int)(off >> 20);
        const float* W = (ws==0)?Wq:(ws==1)?Wk:(ws==2)?Wv:Wo;
        src = W + (off & 1048575u); dh = g_wh; dl = g_wl;
    }
    float4 v = *(const float4*)src;
    uint32_t h0,l0,h1,l1;
    split_pk(v.x,v.y,h0,l0); split_pk(v.z,v.w,h1,l1);
    *(uint32_t*)(dh+off)=h0; *(uint32_t*)(dh+off+2)=h1;
    *(uint32_t*)(dl+off)=l0; *(uint32_t*)(dl+off+2)=l1;
}

__global__ __launch_bounds__(256) void rope_kernel(const float* __restrict__ invf){
    int i = blockIdx.x*256 + threadIdx.x;
    int s = i >> 5, p = i & 31;
    float sn, cs; sincosf((float)s * invf[p], &sn, &cs);
    g_rope[i] = make_float2(cs, sn);
}

// ============================================================
// GEMM: C[128x64], 128 threads, k-chunk 32, 2 stages of 30.7KB
// -> 3 CTAs/SM (12 warps). Same mma structure as R10.
// qkv launch: blockIdx.y<4 = fill blocks (run first).
// ============================================================
#define G_AH 0
#define G_AL 10240
#define G_BH 20480
#define G_BL 25600
#define GSTG 30720
#define GS_SIZE (2*GSTG)   // 61440

__global__ __launch_bounds__(128, 3) void gemm_tc(
    const float* __restrict__ bq, const float* __restrict__ bv,
    const float* __restrict__ bo, float* __restrict__ outp,
    float* __restrict__ qk, int mode_base)
{
    if (mode_base==0 && blockIdx.y < 4) {
        int fid = (int)blockIdx.y*32 + (int)blockIdx.x;
        int bh = fid >> 2, part = fid & 3;
        float* qkp = qk + (size_t)bh*NS*NS;
        const float4 M9 = make_float4(-1e9f,-1e9f,-1e9f,-1e9f);
        for (int qt = part; qt < 31; qt += 4) {
            const int jstart = (qt+1)*64;
            const int n = NS - jstart;
            for (int r = qt*64; r < qt*64 + 64; ++r) {
                float* rp = qkp + (size_t)r*NS + jstart;
                for (int c = (int)threadIdx.x*4; c < n; c += 512)
                    stg_cs4(rp + c, M9);
            }
        }
        return;
    }

    extern __shared__ __align__(128) char sm[];
    const uint32_t smb = smem_u32(sm);
    const int t = threadIdx.x, lane = t&31, wm = t>>5;
    const int m0 = blockIdx.x*128;
    int mode, n0;
    if (mode_base==0) { int y = blockIdx.y-4; mode = y>>4; n0 = (y&15)*64; }
    else { mode = 3; n0 = blockIdx.y*64; }
    const __nv_bfloat16* Ah = (mode_base==0)? g_xh : g_ah;
    const __nv_bfloat16* Al = (mode_base==0)? g_xl : g_al;
    const __nv_bfloat16* Wh = g_wh + (size_t)mode*ND*ND;
    const __nv_bfloat16* Wl = g_wl + (size_t)mode*ND*ND;

    float acc[2][8][4];
#pragma unroll
    for (int i=0;i<2;++i)
#pragma unroll
        for (int j=0;j<8;++j)
#pragma unroll
            for (int q=0;q<4;++q) acc[i][j][q] = 0.f;

    const int lr = t>>2, lc4 = t&3;   // lr 0..31, lc4 0..3 (16B each, 64B row)
    auto issue = [&](int chunk, int buf){
        const int k0 = chunk*32;
        uint32_t sb = smb + buf*GSTG;
#pragma unroll
        for (int i=0;i<4;++i) {
            int r = lr + i*32;
            uint32_t so = (uint32_t)(r*GST2 + lc4*16);
            size_t ga = (size_t)(m0+r)*ND + k0 + lc4*8;
            cpa16(sb + G_AH + so, Ah + ga);
            cpa16(sb + G_AL + so, Al + ga);
        }
#pragma unroll
        for (int i=0;i<2;++i) {
            int r = lr + i*32;
            uint32_t so = (uint32_t)(r*GST2 + lc4*16);
            size_t gw = (size_t)(n0+r)*ND + k0 + lc4*8;
            cpa16(sb + G_BH + so, Wh + gw);
            cpa16(sb + G_BL + so, Wl + gw);
        }
        CPA_COMMIT();
    };

    issue(0, 0);
    for (int c = 0; c < 32; ++c) {
        CPA_WAIT(0);
        __syncthreads();
        if (c < 31) issue(c+1, (c+1)&1);
        uint32_t sb = smb + (c&1)*GSTG;
#pragma unroll
        for (int kk = 0; kk < 2; ++kk) {
            const int kb = kk*16;
            uint32_t ah[2][4], al[2][4], bh16[16], bl16[16];
#pragma unroll
            for (int mt=0;mt<2;++mt) {
                ldsm4(ah[mt], addrA(sb+G_AH, wm*32+mt*16, kb, lane, GST2));
                ldsm4(al[mt], addrA(sb+G_AL, wm*32+mt*16, kb, lane, GST2));
            }
#pragma unroll
            for (int tn=0;tn<4;++tn) {
                ldsm4(&bh16[tn*4], addrB(sb+G_BH, tn*16, kb, lane, GST2));
                ldsm4(&bl16[tn*4], addrB(sb+G_BL, tn*16, kb, lane, GST2));
            }
#pragma unroll
            for (int mt=0;mt<2;++mt)
#pragma unroll
                for (int nt=0;nt<8;++nt)
                    mma16816(acc[mt][nt], ah[mt], bh16[(nt>>1)*4+(nt&1)*2], bh16[(nt>>1)*4+(nt&1)*2+1]);
#pragma unroll
            for (int mt=0;mt<2;++mt)
#pragma unroll
                for (int nt=0;nt<8;++nt)
                    mma16816(acc[mt][nt], ah[mt], bl16[(nt>>1)*4+(nt&1)*2], bl16[(nt>>1)*4+(nt&1)*2+1]);
#pragma unroll
            for (int mt=0;mt<2;++mt)
#pragma unroll
                for (int nt=0;nt<8;++nt)
                    mma16816(acc[mt][nt], al[mt], bh16[(nt>>1)*4+(nt&1)*2], bh16[(nt>>1)*4+(nt&1)*2+1]);
        }
    }

#pragma unroll
    for (int mt=0;mt<2;++mt)
#pragma unroll
        for (int nt=0;nt<8;++nt) {
            int rowb = wm*32 + mt*16 + (lane>>2);
            int col  = n0 + nt*8 + ((lane&3)<<1);
            float bb0 = 0.f, bb1 = 0.f;
            if (mode==0)      { bb0 = bq[col]; bb1 = bq[col+1]; }
            else if (mode==2) { bb0 = bv[col]; bb1 = bv[col+1]; }
            else if (mode==3) { bb0 = bo[col]; bb1 = bo[col+1]; }
#pragma unroll
            for (int h=0;h<2;++h) {
                int m = m0 + rowb + h*8;
                float v0 = acc[mt][nt][h*2]   + bb0;
                float v1 = acc[mt][nt][h*2+1] + bb1;
                int b = m>>11, s = m&(NS-1);
                if (mode<=1) {
                    float2 cs = g_rope[s*32 + ((col&63)>>1)];
                    float a = v0, b2 = v1;
                    v0 = (a*cs.x - b2*cs.y)*ROT_SCALE;
                    v1 = (a*cs.y + b2*cs.x)*ROT_SCALE;
                }
                if (mode==3) {
                    *(float2*)(outp + (size_t)m*ND + col) = make_float2(v0, v1);
                } else {
                    int hh = col>>6, bh = b*NH + hh, d0 = col&63;
                    size_t off = ((size_t)bh*NS + s)*HD + d0;
                    uint32_t hi, lo;
                    split_pk(v0, v1, hi, lo);
                    __nv_bfloat16 *dh = (mode==0)?g_qh:(mode==1)?g_kh:g_vh;
                    __nv_bfloat16 *dl = (mode==0)?g_ql:(mode==1)?g_kl:g_vl;
                    *(uint32_t*)(dh+off) = hi;
                    *(uint32_t*)(dl+off) = lo;
                }
            }
        }
}

// ============================================================
// Attention: R10 version verbatim (known 211.6us; do not touch).
// ============================================================
#define A_KH 0
#define A_KL 9216
#define A_VH 18432
#define A_VL 27648
#define ASTG 36864
#define AS_SIZE (3*ASTG)   // 110592

__global__ __launch_bounds__(128, 2) void attn_tc(float* __restrict__ qk)
{
    extern __shared__ __align__(128) char sm[];
    const uint32_t smb = smem_u32(sm);
    const int t = threadIdx.x, lane = t&31, wm = t>>5;
    const int qt = (int)gridDim.x - 1 - (int)blockIdx.x;
    const int bh = blockIdx.y;
    const int i0 = qt*64;
    float* __restrict__ qkp = qk + (size_t)bh*NS*NS;

    const int lr = t>>3, lc8 = t&7;
    auto issue = [&](int kt){
        uint32_t sb = smb + (uint32_t)(kt%3)*ASTG;
#pragma unroll
        for (int i=0;i<4;++i) {
            int r = lr + i*16;
            uint32_t so = (uint32_t)(r*SMST + lc8*16);
            size_t go = ((size_t)bh*NS + kt*64 + r)*HD + lc8*8;
            cpa16(sb + A_KH + so, g_kh + go);
            cpa16(sb + A_KL + so, g_kl + go);
            cpa16(sb + A_VH + so, g_vh + go);
            cpa16(sb + A_VL + so, g_vl + go);
        }
        CPA_COMMIT();
    };

#pragma unroll
    for (int i=0;i<4;++i) {
        int r = lr + i*16;
        uint32_t so = (uint32_t)(r*SMST + lc8*16);
        size_t go = ((size_t)bh*NS + i0 + r)*HD + lc8*8;
        *(uint4*)(sm + A_KH + so) = *(const uint4*)(g_qh + go);
        *(uint4*)(sm + A_KL + so) = *(const uint4*)(g_ql + go);
    }
    __syncthreads();
    uint32_t qfh[4][4], qfl[4][4];
#pragma unroll
    for (int kk=0;kk<4;++kk) {
        ldsm4(qfh[kk], addrA(smb + A_KH, wm*16, kk*16, lane, SMST));
        ldsm4(qfl[kk], addrA(smb + A_KL, wm*16, kk*16, lane, SMST));
    }
    __syncthreads();
    issue(0);
    if (qt >= 1) issue(1);

    float o[8][4];
#pragma unroll
    for (int n=0;n<8;++n)
#pragma unroll
        for (int q=0;q<4;++q) o[n][q] = 0.f;
    float l0 = 0.f, l1 = 0.f;

    const int r0 = lane>>2;
    const int irow0 = i0 + wm*16 + r0;
    const int irow1 = irow0 + 8;
    const int cql = (lane&3)<<1;

    float sprev[8][4], scur[8][4];

    auto pv = [&](float (*sacc)[4], int kts, int gmax, int kmax2){
        uint32_t sb = smb + (uint32_t)(kts%3)*ASTG;
        float* qrow0 = qkp + (size_t)irow0*NS + kts*64 + cql;
        float* qrow1 = qkp + (size_t)irow1*NS + kts*64 + cql;
#pragma unroll
        for (int j=0;j<8;++j) {
            stg_cs2(qrow0 + j*8, sacc[j][0], sacc[j][1]);
            stg_cs2(qrow1 + j*8, sacc[j][2], sacc[j][3]);
        }
#pragma unroll
        for (int g=0; g<2; ++g) {
            if (g >= gmax) break;
            uint32_t vh[8][4], vl[8][4];
#pragma unroll
            for (int n=0;n<8;++n) {
                ldsm4t(vh[n], addrVt(sb+A_VH, g*32, n*8, lane, SMST));
                ldsm4t(vl[n], addrVt(sb+A_VL, g*32, n*8, lane, SMST));
            }
#pragma unroll
            for (int sub=0; sub<2; ++sub) {
                const int kk2 = g*2 + sub;
                if (kk2 >= kmax2) continue;
                const int j0 = 2*kk2, j1 = j0+1;
                float p00 = __expf(sacc[j0][0]), p01 = __expf(sacc[j0][1]);
                float p02 = __expf(sacc[j0][2]), p03 = __expf(sacc[j0][3]);
                float p10 = __expf(sacc[j1][0]), p11 = __expf(sacc[j1][1]);
                float p12 = __expf(sacc[j1][2]), p13 = __expf(sacc[j1][3]);
                l0 += (p00 + p01) + (p10 + p11);
                l1 += (p02 + p03) + (p12 + p13);
                uint32_t a0h,a0l,b0h,b0l,a1h,a1l,b1h,b1l;
                split_pk(p00, p01, a0h, a0l);
                split_pk(p02, p03, b0h, b0l);
                split_pk(p10, p11, a1h, a1l);
                split_pk(p12, p13, b1h, b1l);
#pragma unroll
                for (int n=0;n<8;++n)
                    mma16816v(o[n], a0h, b0h, a1h, b1h, vh[n][sub*2], vh[n][sub*2+1]);
#pragma unroll
                for (int n=0;n<8;++n)
                    mma16816v(o[n], a0h, b0h, a1h, b1h, vl[n][sub*2], vl[n][sub*2+1]);
#pragma unroll
                for (int n=0;n<8;++n)
                    mma16816v(o[n], a0l, b0l, a1l, b1l, vh[n][sub*2], vh[n][sub*2+1]);
            }
        }
    };

    for (int kt = 0; kt <= qt; ++kt) {
        if (kt < qt) { CPA_WAIT(1); } else { CPA_WAIT(0); }
        __syncthreads();
        uint32_t sb = smb + (uint32_t)(kt%3)*ASTG;
        const bool diag = (kt == qt);
        const int jmax = diag ? (2*wm + 2) : 8;
        const int tmax = diag ? (wm + 1)  : 4;

#pragma unroll
        for (int j=0;j<8;++j)
#pragma unroll
            for (int q=0;q<4;++q) scur[j][q] = -1e9f;
#pragma unroll
        for (int j=0;j<8;++j)
            if (j < jmax)
#pragma unroll
                for (int q=0;q<4;++q) scur[j][q] = 0.f;
#pragma unroll
        for (int kk=0;kk<4;++kk) {
            const int kb = kk*16;
            uint32_t kh16[16], kl16[16];
#pragma unroll
            for (int tn=0;tn<4;++tn) {
                if (tn < tmax) {
                    ldsm4(&kh16[tn*4], addrB(sb+A_KH, tn*16, kb, lane, SMST));
                    ldsm4(&kl16[tn*4], addrB(sb+A_KL, tn*16, kb, lane, SMST));
                }
            }
#pragma unroll
            for (int j=0;j<8;++j)
                if (j < jmax) mma16816(scur[j], qfh[kk], kh16[(j>>1)*4+(j&1)*2], kh16[(j>>1)*4+(j&1)*2+1]);
#pragma unroll
            for (int j=0;j<8;++j)
                if (j < jmax) mma16816(scur[j], qfh[kk], kl16[(j>>1)*4+(j&1)*2], kl16[(j>>1)*4+(j&1)*2+1]);
#pragma unroll
            for (int j=0;j<8;++j)
                if (j < jmax) mma16816(scur[j], qfl[kk], kh16[(j>>1)*4+(j&1)*2], kh16[(j>>1)*4+(j&1)*2+1]);
        }

        if (kt > 0) pv(sprev, kt-1, 2, 4);

        __syncthreads();
        if (kt+2 <= qt) issue(kt+2);

#pragma unroll
        for (int j=0;j<8;++j)
#pragma unroll
            for (int q=0;q<4;++q) sprev[j][q] = scur[j][q];
    }

    {
#pragma unroll
        for (int j=0;j<8;++j) {
            int jc = qt*64 + j*8 + cql;
            if (jc   > irow0) sprev[j][0] = -1e9f;
            if (jc+1 > irow0) sprev[j][1] = -1e9f;
            if (jc   > irow1) sprev[j][2] = -1e9f;
            if (jc+1 > irow1) sprev[j][3] = -1e9f;
        }
        pv(sprev, qt, (wm>>1)+1, wm+1);
    }

    l0 += __shfl_xor_sync(0xffffffffu, l0, 1);
    l0 += __shfl_xor_sync(0xffffffffu, l0, 2);
    l1 += __shfl_xor_sync(0xffffffffu, l1, 1);
    l1 += __shfl_xor_sync(0xffffffffu, l1, 2);
    const int b = bh>>4, hh = bh&15;
    const float li0 = 1.f / l0, li1 = 1.f / l1;
#pragma unroll
    for (int n=0;n<8;++n) {
        uint32_t hi, lo;
        float v0 = o[n][0]*li0, v1 = o[n][1]*li0;
        split_pk(v0, v1, hi, lo);
        size_t off0 = ((size_t)(b*NS + irow0))*ND + hh*HD + n*8 + cql;
        *(uint32_t*)(g_ah + off0) = hi;
        *(uint32_t*)(g_al + off0) = lo;
        float v2 = o[n][2]*li1, v3 = o[n][3]*li1;
        split_pk(v2, v3, hi, lo);
        size_t off1 = ((size_t)(b*NS + irow1))*ND + hh*HD + n*8 + cql;
        *(uint32_t*)(g_ah + off1) = hi;
        *(uint32_t*)(g_al + off1) = lo;
    }
}

// ---------------- launch ----------------
extern "C" void kernel_launch(void* const* d_in, const int* in_sizes, int n_in,
                              void* d_out, int out_size)
{
    const float* x    = (const float*)d_in[0];
    const float* Wq   = (const float*)d_in[2];
    const float* bq   = (const float*)d_in[3];
    const float* Wk   = (const float*)d_in[4];
    const float* Wv   = (const float*)d_in[5];
    const float* bv   = (const float*)d_in[6];
    const float* Wo   = (const float*)d_in[7];
    const float* bo   = (const float*)d_in[8];
    const float* invf = (const float*)d_in[9];

    float* out = (float*)d_out;
    float* qk  = out + (size_t)NM*ND;

    cudaFuncSetAttribute((const void*)gemm_tc, cudaFuncAttributeMaxDynamicSharedMemorySize, GS_SIZE);
    cudaFuncSetAttribute((const void*)attn_tc, cudaFuncAttributeMaxDynamicSharedMemorySize, AS_SIZE);

    prep_kernel<<<8192, 256>>>(x, Wq, Wk, Wv, Wo);
    rope_kernel<<<256, 256>>>(invf);
    gemm_tc<<<dim3(32,52), 128, GS_SIZE>>>(bq, bv, bo, nullptr, qk, 0);  // fill(y<4) + qkv
    attn_tc<<<dim3(32,32), 128, AS_SIZE>>>(qk);
    gemm_tc<<<dim3(32,16), 128, GS_SIZE>>>(bq, bv, bo, out, qk, 1);      // out proj
}